// round 2
// baseline (speedup 1.0000x reference)
#include <cuda_runtime.h>
#include <math.h>

// Problem constants
#define BB 2
#define SS 4096
#define EE 512
#define HH 8
#define DD 64
#define WW 512
#define NWIN 8            // SS / WW
#define NBUCKETS 32

#define NEGINF (-INFINITY)

// Scratch: q,k,v in [b][h][s][d] layout (16 MB each)
__device__ float g_q[BB*HH*SS*DD];
__device__ float g_k[BB*HH*SS*DD];
__device__ float g_v[BB*HH*SS*DD];

// ---------------------------------------------------------------------------
// Projection: out[b][h][s][d] = sum_e xs[b,s,e] * w[e,h,d]   (q scaled 0.125)
// SGEMM: M=8192 (b*s), N=512 (h*d), K=512.  128x128 tile, 8x8 microtile.
// ---------------------------------------------------------------------------
__global__ __launch_bounds__(256) void proj_kernel(
    const float* __restrict__ xs,
    const float* __restrict__ wq,
    const float* __restrict__ wk,
    const float* __restrict__ wv)
{
    const int zb = blockIdx.z;
    const float* w   = (zb == 0) ? wq : (zb == 1) ? wk : wv;
    float*       out = (zb == 0) ? g_q : (zb == 1) ? g_k : g_v;
    const float scale = (zb == 0) ? 0.125f : 1.0f;   // 1/sqrt(D)

    __shared__ __align__(16) float As[16][128];   // [k][m]
    __shared__ __align__(16) float Bs[16][128];   // [k][n]

    const int m0 = blockIdx.x * 128;
    const int n0 = blockIdx.y * 128;
    const int tid = threadIdx.x;
    const int tr = tid / 16;     // 0..15
    const int tc = tid % 16;     // 0..15

    float acc[8][8];
    #pragma unroll
    for (int i = 0; i < 8; i++)
        #pragma unroll
        for (int j = 0; j < 8; j++) acc[i][j] = 0.0f;

    for (int k0 = 0; k0 < EE; k0 += 16) {
        // Load A tile (128 rows x 16 k) transposed into As[k][m]
        #pragma unroll
        for (int i = 0; i < 2; i++) {
            int idx = tid + i * 256;           // 0..511
            int row = idx >> 2;                // 0..127
            int c4  = idx & 3;                 // 0..3
            float4 v = *(const float4*)(xs + (size_t)(m0 + row) * EE + k0 + c4 * 4);
            As[c4*4+0][row] = v.x;
            As[c4*4+1][row] = v.y;
            As[c4*4+2][row] = v.z;
            As[c4*4+3][row] = v.w;
        }
        // Load B tile (16 k x 128 n)
        #pragma unroll
        for (int i = 0; i < 2; i++) {
            int idx = tid + i * 256;           // 0..511
            int row = idx >> 5;                // 0..15
            int c4  = idx & 31;                // 0..31
            float4 v = *(const float4*)(w + (size_t)(k0 + row) * (HH*DD) + n0 + c4 * 4);
            *(float4*)&Bs[row][c4 * 4] = v;
        }
        __syncthreads();

        #pragma unroll
        for (int kk = 0; kk < 16; kk++) {
            float a[8], b[8];
            float4 a0 = *(const float4*)&As[kk][tr * 8];
            float4 a1 = *(const float4*)&As[kk][tr * 8 + 4];
            float4 b0 = *(const float4*)&Bs[kk][tc * 8];
            float4 b1 = *(const float4*)&Bs[kk][tc * 8 + 4];
            a[0]=a0.x; a[1]=a0.y; a[2]=a0.z; a[3]=a0.w;
            a[4]=a1.x; a[5]=a1.y; a[6]=a1.z; a[7]=a1.w;
            b[0]=b0.x; b[1]=b0.y; b[2]=b0.z; b[3]=b0.w;
            b[4]=b1.x; b[5]=b1.y; b[6]=b1.z; b[7]=b1.w;
            #pragma unroll
            for (int i = 0; i < 8; i++)
                #pragma unroll
                for (int j = 0; j < 8; j++)
                    acc[i][j] += a[i] * b[j];
        }
        __syncthreads();
    }

    // Epilogue: scatter into [b][h][s][d].  Tile never straddles batch
    // (128 | 4096), and 8-wide col group never straddles a head (8 | 64).
    const int b = m0 / SS;
    const int cbase = n0 + tc * 8;
    const int h = cbase / DD;
    const int d = cbase % DD;
    #pragma unroll
    for (int i = 0; i < 8; i++) {
        int m = m0 + tr * 8 + i;
        int s = m - b * SS;
        float* dst = out + (((size_t)(b * HH + h) * SS + s) * DD + d);
        #pragma unroll
        for (int j = 0; j < 8; j++) dst[j] = acc[i][j] * scale;
    }
}

// ---------------------------------------------------------------------------
// Attention: sliding-window causal (key g in (p-W, p]) with T5 relative bias.
// One thread per query; online softmax with conditional rescale.
// Block = 128 threads = 128 queries; grid = (4 chunks, H, B*nw).
// ---------------------------------------------------------------------------
__global__ __launch_bounds__(128) void attn_kernel(
    const float* __restrict__ prev_k,
    const float* __restrict__ prev_v,
    const float* __restrict__ rel_bias,
    float* __restrict__ out)
{
    const int chunk = blockIdx.x;          // 0..3
    const int h     = blockIdx.y;          // 0..7
    const int bn    = blockIdx.z;          // 0..15
    const int b = bn / NWIN;
    const int n = bn % NWIN;
    const int t = threadIdx.x;

    __shared__ __align__(16) float Ks[64][64];
    __shared__ __align__(16) float Vs[64][64];
    __shared__ float bias_s[WW];

    // Build per-head bias table: bias_s[nrel] for nrel = (query - key) in [0, W)
    for (int i = t; i < WW; i += 128) {
        int bucket;
        if (i < 16) {
            bucket = i;
        } else {
            float nf = (float)i;
            float tv = logf(nf * 0.0625f) / 2.0794415416798357f * 16.0f;
            int vi = 16 + (int)tv;
            bucket = (vi < NBUCKETS - 1) ? vi : (NBUCKETS - 1);
        }
        bias_s[i] = rel_bias[h * NBUCKETS + bucket];
    }

    const int q0 = n * WW + chunk * 128;     // first query (abs) of this block
    const int p  = q0 + t;                   // this thread's query position

    // Load query row into registers
    float qreg[64];
    {
        const float* qp = g_q + (((size_t)(b * HH + h) * SS + p) * DD);
        #pragma unroll
        for (int i = 0; i < 16; i++)
            ((float4*)qreg)[i] = *(const float4*)(qp + i * 4);
    }

    float acc[64];
    #pragma unroll
    for (int d = 0; d < 64; d++) acc[d] = 0.0f;
    float mrun = -1e30f;
    float lrun = 0.0f;

    const int kt0 = q0 - WW;                 // first key tile start
    const int pbase = q0 + (t & ~31);        // warp's first query

    for (int tile = 0; tile < 10; tile++) {
        const int kt = kt0 + tile * 64;
        __syncthreads();
        // Cooperative load of 64 keys + 64 values (each thread 8+8 float4)
        for (int i = t; i < 64 * 16; i += 128) {
            int row = i >> 4;
            int c4  = i & 15;
            int g = kt + row;
            const float *sk, *sv;
            if (g < 0) {   // previous-window K/V (only window 0)
                size_t off = (((size_t)(b * WW + (g + WW)) * HH + h) * DD) + c4 * 4;
                sk = prev_k + off;  sv = prev_v + off;
            } else {
                size_t off = (((size_t)(b * HH + h) * SS + g) * DD) + c4 * 4;
                sk = g_k + off;     sv = g_v + off;
            }
            *(float4*)&Ks[row][c4 * 4] = *(const float4*)sk;
            *(float4*)&Vs[row][c4 * 4] = *(const float4*)sv;
        }
        __syncthreads();

        // Warp-uniform loop bounds (keeps Ks/Vs reads broadcast)
        int jloW = pbase - (WW - 1) - kt; if (jloW < 0) jloW = 0;
        int jhiW = pbase + 31 - kt;       if (jhiW > 63) jhiW = 63;

        for (int j = jloW; j <= jhiW; j++) {
            int rel = p - (kt + j);                       // query - key
            bool act = (rel >= 0) && (rel < WW);
            float s = act ? bias_s[rel & (WW - 1)] : NEGINF;

            const float* kr = &Ks[j][0];
            float d0 = 0.f, d1 = 0.f, d2 = 0.f, d3 = 0.f;
            #pragma unroll
            for (int d4 = 0; d4 < 16; d4++) {
                float4 kv = *(const float4*)(kr + d4 * 4);
                d0 += qreg[d4*4+0] * kv.x;
                d1 += qreg[d4*4+1] * kv.y;
                d2 += qreg[d4*4+2] * kv.z;
                d3 += qreg[d4*4+3] * kv.w;
            }
            s += (d0 + d1) + (d2 + d3);

            if (s > mrun) {                 // rare: rescale running state
                float c = __expf(mrun - s);
                lrun *= c;
                #pragma unroll
                for (int d = 0; d < 64; d++) acc[d] *= c;
                mrun = s;
            }
            float pw = __expf(s - mrun);    // 0 for masked (s = -inf)
            lrun += pw;

            const float* vr = &Vs[j][0];
            #pragma unroll
            for (int d4 = 0; d4 < 16; d4++) {
                float4 vv = *(const float4*)(vr + d4 * 4);
                acc[d4*4+0] += pw * vv.x;
                acc[d4*4+1] += pw * vv.y;
                acc[d4*4+2] += pw * vv.z;
                acc[d4*4+3] += pw * vv.w;
            }
        }
    }

    // Write attn output: (B, S, H, D)
    const float inv = 1.0f / lrun;
    float* op = out + (((size_t)(b * SS + p) * HH + h) * DD);
    #pragma unroll
    for (int d4 = 0; d4 < 16; d4++) {
        float4 o;
        o.x = acc[d4*4+0] * inv;
        o.y = acc[d4*4+1] * inv;
        o.z = acc[d4*4+2] * inv;
        o.w = acc[d4*4+3] * inv;
        *(float4*)(op + d4 * 4) = o;
    }
}

// ---------------------------------------------------------------------------
// Tail: next_k / next_v = last window of k / v, layout (B, W, H, D)
// ---------------------------------------------------------------------------
__global__ __launch_bounds__(256) void tail_kernel(float* __restrict__ out)
{
    const size_t OFF_K = (size_t)BB * SS * HH * DD;             // 4194304
    const size_t OFF_V = OFF_K + (size_t)BB * WW * HH * DD;     // 4718592
    int i = blockIdx.x * 256 + threadIdx.x;                     // < 524288
    int b = i / (WW * HH * DD);
    int r = i % (WW * HH * DD);
    int w = r / (HH * DD);
    int r2 = r % (HH * DD);
    int h = r2 / DD;
    int d = r2 % DD;
    size_t src = (((size_t)(b * HH + h) * SS + (SS - WW + w)) * DD + d);
    out[OFF_K + i] = g_k[src];
    out[OFF_V + i] = g_v[src];
}

// ---------------------------------------------------------------------------
extern "C" void kernel_launch(void* const* d_in, const int* in_sizes, int n_in,
                              void* d_out, int out_size)
{
    const float* xs       = (const float*)d_in[0];
    const float* prev_k   = (const float*)d_in[1];
    const float* prev_v   = (const float*)d_in[2];
    const float* w_q      = (const float*)d_in[3];
    const float* w_k      = (const float*)d_in[4];
    const float* w_v      = (const float*)d_in[5];
    const float* rel_bias = (const float*)d_in[6];
    float* out = (float*)d_out;

    dim3 pg(64, 4, 3);                 // M/128, N/128, {q,k,v}
    proj_kernel<<<pg, 256>>>(xs, w_q, w_k, w_v);

    dim3 ag(4, HH, BB * NWIN);         // query chunks, heads, batch*windows
    attn_kernel<<<ag, 128>>>(prev_k, prev_v, rel_bias, out);

    tail_kernel<<<2048, 256>>>(out);
}

// round 3
// speedup vs baseline: 1.0065x; 1.0065x over previous
#include <cuda_runtime.h>
#include <math.h>

// Problem constants
#define BB 2
#define SS 4096
#define EE 512
#define HH 8
#define DD 64
#define WW 512
#define NWIN 8            // SS / WW
#define NBUCKETS 32

#define NEGINF (-INFINITY)

// Scratch: q,k,v in [b][h][s][d] layout (16 MB each)
__device__ float g_q[BB*HH*SS*DD];
__device__ float g_k[BB*HH*SS*DD];
__device__ float g_v[BB*HH*SS*DD];

// ---------------------------------------------------------------------------
// tf32 helpers
// ---------------------------------------------------------------------------
__device__ __forceinline__ unsigned f2tf32(float x) {
    unsigned r;
    asm("cvt.rna.tf32.f32 %0, %1;" : "=r"(r) : "f"(x));
    return r;
}

__device__ __forceinline__ void mma_tf32(float c[4], const unsigned a[4], const unsigned b[2]) {
    asm volatile(
        "mma.sync.aligned.m16n8k8.row.col.f32.tf32.tf32.f32 "
        "{%0,%1,%2,%3}, {%4,%5,%6,%7}, {%8,%9}, {%0,%1,%2,%3};"
        : "+f"(c[0]), "+f"(c[1]), "+f"(c[2]), "+f"(c[3])
        : "r"(a[0]), "r"(a[1]), "r"(a[2]), "r"(a[3]), "r"(b[0]), "r"(b[1]));
}

// ---------------------------------------------------------------------------
// Projection via 3xTF32 tensor-core GEMM.
// out[b][h][s][d] = sum_e xs[b,s,e] * w[e,h,d]   (q scaled 0.125)
// M=8192 (b*s), N=512 (h*d), K=512.  128x128 block tile, 8 warps (2x4),
// warp tile 64x32, k-chunk 16.  SMEM stride 20 -> conflict-free frag loads.
// ---------------------------------------------------------------------------
#define KC 16
#define SSTR 20

__global__ __launch_bounds__(256, 1) void proj_kernel(
    const float* __restrict__ xs,
    const float* __restrict__ wq,
    const float* __restrict__ wk,
    const float* __restrict__ wv)
{
    const int zb = blockIdx.z;
    const float* w   = (zb == 0) ? wq : (zb == 1) ? wk : wv;
    float*       out = (zb == 0) ? g_q : (zb == 1) ? g_k : g_v;
    const float scale = (zb == 0) ? 0.125f : 1.0f;   // 1/sqrt(D)

    __shared__ float As_hi[128 * SSTR];
    __shared__ float As_lo[128 * SSTR];
    __shared__ float Bs_hi[128 * SSTR];   // indexed [n][k]
    __shared__ float Bs_lo[128 * SSTR];

    const int m0 = blockIdx.x * 128;
    const int n0 = blockIdx.y * 128;
    const int tid  = threadIdx.x;
    const int wid  = tid >> 5;
    const int lane = tid & 31;
    const int g    = lane >> 2;     // groupID 0..7
    const int tg   = lane & 3;      // thread in group 0..3
    const int wm   = wid >> 2;      // 0..1
    const int wn   = wid & 3;       // 0..3

    float acc[4][4][4];
    #pragma unroll
    for (int mt = 0; mt < 4; mt++)
        #pragma unroll
        for (int nt = 0; nt < 4; nt++)
            #pragma unroll
            for (int r = 0; r < 4; r++) acc[mt][nt][r] = 0.0f;

    for (int k0 = 0; k0 < EE; k0 += KC) {
        __syncthreads();
        // --- Stage A tile (128 rows x 16 k), split hi/lo ---
        #pragma unroll
        for (int i = 0; i < 2; i++) {
            int idx = tid + i * 256;           // 0..511
            int row = idx >> 2;                // 0..127
            int c4  = idx & 3;                 // 0..3
            float4 v = *(const float4*)(xs + (size_t)(m0 + row) * EE + k0 + c4 * 4);
            float xv[4] = {v.x, v.y, v.z, v.w};
            #pragma unroll
            for (int j = 0; j < 4; j++) {
                unsigned hi = f2tf32(xv[j]);
                unsigned lo = f2tf32(xv[j] - __uint_as_float(hi));
                As_hi[row * SSTR + c4 * 4 + j] = __uint_as_float(hi);
                As_lo[row * SSTR + c4 * 4 + j] = __uint_as_float(lo);
            }
        }
        // --- Stage B tile (16 k x 128 n) transposed into [n][k], split ---
        #pragma unroll
        for (int i = 0; i < 2; i++) {
            int krow = (tid >> 5) + (i << 3);  // 0..15
            int c4   = tid & 31;
            #pragma unroll
            for (int j = 0; j < 4; j++) {
                int n = c4 + 32 * j;           // 0..127, coalesced per j
                float x = w[(size_t)(k0 + krow) * (HH * DD) + n0 + n];
                unsigned hi = f2tf32(x);
                unsigned lo = f2tf32(x - __uint_as_float(hi));
                Bs_hi[n * SSTR + krow] = __uint_as_float(hi);
                Bs_lo[n * SSTR + krow] = __uint_as_float(lo);
            }
        }
        __syncthreads();

        // --- Two k8 MMA steps ---
        #pragma unroll
        for (int ks = 0; ks < KC; ks += 8) {
            unsigned ah[4][4], al[4][4], bh[4][2], bl[4][2];
            #pragma unroll
            for (int mt = 0; mt < 4; mt++) {
                int r0 = (wm * 64 + mt * 16 + g) * SSTR;
                int r1 = r0 + 8 * SSTR;
                ah[mt][0] = __float_as_uint(As_hi[r0 + ks + tg]);
                ah[mt][1] = __float_as_uint(As_hi[r1 + ks + tg]);
                ah[mt][2] = __float_as_uint(As_hi[r0 + ks + tg + 4]);
                ah[mt][3] = __float_as_uint(As_hi[r1 + ks + tg + 4]);
                al[mt][0] = __float_as_uint(As_lo[r0 + ks + tg]);
                al[mt][1] = __float_as_uint(As_lo[r1 + ks + tg]);
                al[mt][2] = __float_as_uint(As_lo[r0 + ks + tg + 4]);
                al[mt][3] = __float_as_uint(As_lo[r1 + ks + tg + 4]);
            }
            #pragma unroll
            for (int nt = 0; nt < 4; nt++) {
                int c0 = (wn * 32 + nt * 8 + g) * SSTR;
                bh[nt][0] = __float_as_uint(Bs_hi[c0 + ks + tg]);
                bh[nt][1] = __float_as_uint(Bs_hi[c0 + ks + tg + 4]);
                bl[nt][0] = __float_as_uint(Bs_lo[c0 + ks + tg]);
                bl[nt][1] = __float_as_uint(Bs_lo[c0 + ks + tg + 4]);
            }
            #pragma unroll
            for (int mt = 0; mt < 4; mt++)
                #pragma unroll
                for (int nt = 0; nt < 4; nt++) {
                    mma_tf32(acc[mt][nt], ah[mt], bh[nt]);
                    mma_tf32(acc[mt][nt], ah[mt], bl[nt]);
                    mma_tf32(acc[mt][nt], al[mt], bh[nt]);
                }
        }
    }

    // --- Epilogue: scatter to [b][h][s][d] ---
    const int b = m0 / SS;
    #pragma unroll
    for (int mt = 0; mt < 4; mt++) {
        int m_lo = m0 + wm * 64 + mt * 16 + g;     // rows g and g+8
        #pragma unroll
        for (int nt = 0; nt < 4; nt++) {
            int n = n0 + wn * 32 + nt * 8 + tg * 2;
            int h = n / DD;
            int d = n % DD;
            {
                int s = m_lo - b * SS;
                float2 v; v.x = acc[mt][nt][0] * scale; v.y = acc[mt][nt][1] * scale;
                *(float2*)(out + (((size_t)(b * HH + h) * SS + s) * DD + d)) = v;
            }
            {
                int s = m_lo + 8 - b * SS;
                float2 v; v.x = acc[mt][nt][2] * scale; v.y = acc[mt][nt][3] * scale;
                *(float2*)(out + (((size_t)(b * HH + h) * SS + s) * DD + d)) = v;
            }
        }
    }
}

// ---------------------------------------------------------------------------
// Attention: sliding-window causal (key g in (p-W, p]) with T5 relative bias.
// One thread per query; online softmax with conditional rescale.
// Block = 128 threads = 128 queries; grid = (4 chunks, H, B*nw).
// ---------------------------------------------------------------------------
__global__ __launch_bounds__(128) void attn_kernel(
    const float* __restrict__ prev_k,
    const float* __restrict__ prev_v,
    const float* __restrict__ rel_bias,
    float* __restrict__ out)
{
    const int chunk = blockIdx.x;          // 0..3
    const int h     = blockIdx.y;          // 0..7
    const int bn    = blockIdx.z;          // 0..15
    const int b = bn / NWIN;
    const int n = bn % NWIN;
    const int t = threadIdx.x;

    __shared__ __align__(16) float Ks[64][64];
    __shared__ __align__(16) float Vs[64][64];
    __shared__ float bias_s[WW];

    // Build per-head bias table: bias_s[nrel] for nrel = (query - key) in [0, W)
    for (int i = t; i < WW; i += 128) {
        int bucket;
        if (i < 16) {
            bucket = i;
        } else {
            float nf = (float)i;
            float tv = logf(nf * 0.0625f) / 2.0794415416798357f * 16.0f;
            int vi = 16 + (int)tv;
            bucket = (vi < NBUCKETS - 1) ? vi : (NBUCKETS - 1);
        }
        bias_s[i] = rel_bias[h * NBUCKETS + bucket];
    }

    const int q0 = n * WW + chunk * 128;     // first query (abs) of this block
    const int p  = q0 + t;                   // this thread's query position

    // Load query row into registers
    float qreg[64];
    {
        const float* qp = g_q + (((size_t)(b * HH + h) * SS + p) * DD);
        #pragma unroll
        for (int i = 0; i < 16; i++)
            ((float4*)qreg)[i] = *(const float4*)(qp + i * 4);
    }

    float acc[64];
    #pragma unroll
    for (int d = 0; d < 64; d++) acc[d] = 0.0f;
    float mrun = -1e30f;
    float lrun = 0.0f;

    const int kt0 = q0 - WW;                 // first key tile start
    const int pbase = q0 + (t & ~31);        // warp's first query

    for (int tile = 0; tile < 10; tile++) {
        const int kt = kt0 + tile * 64;
        __syncthreads();
        // Cooperative load of 64 keys + 64 values (each thread 8+8 float4)
        for (int i = t; i < 64 * 16; i += 128) {
            int row = i >> 4;
            int c4  = i & 15;
            int g = kt + row;
            const float *sk, *sv;
            if (g < 0) {   // previous-window K/V (only window 0)
                size_t off = (((size_t)(b * WW + (g + WW)) * HH + h) * DD) + c4 * 4;
                sk = prev_k + off;  sv = prev_v + off;
            } else {
                size_t off = (((size_t)(b * HH + h) * SS + g) * DD) + c4 * 4;
                sk = g_k + off;     sv = g_v + off;
            }
            *(float4*)&Ks[row][c4 * 4] = *(const float4*)sk;
            *(float4*)&Vs[row][c4 * 4] = *(const float4*)sv;
        }
        __syncthreads();

        // Warp-uniform loop bounds (keeps Ks/Vs reads broadcast)
        int jloW = pbase - (WW - 1) - kt; if (jloW < 0) jloW = 0;
        int jhiW = pbase + 31 - kt;       if (jhiW > 63) jhiW = 63;

        for (int j = jloW; j <= jhiW; j++) {
            int rel = p - (kt + j);                       // query - key
            bool act = (rel >= 0) && (rel < WW);
            float s = act ? bias_s[rel & (WW - 1)] : NEGINF;

            const float* kr = &Ks[j][0];
            float d0 = 0.f, d1 = 0.f, d2 = 0.f, d3 = 0.f;
            #pragma unroll
            for (int d4 = 0; d4 < 16; d4++) {
                float4 kv = *(const float4*)(kr + d4 * 4);
                d0 += qreg[d4*4+0] * kv.x;
                d1 += qreg[d4*4+1] * kv.y;
                d2 += qreg[d4*4+2] * kv.z;
                d3 += qreg[d4*4+3] * kv.w;
            }
            s += (d0 + d1) + (d2 + d3);

            if (s > mrun) {                 // rare: rescale running state
                float c = __expf(mrun - s);
                lrun *= c;
                #pragma unroll
                for (int d = 0; d < 64; d++) acc[d] *= c;
                mrun = s;
            }
            float pw = __expf(s - mrun);    // 0 for masked (s = -inf)
            lrun += pw;

            const float* vr = &Vs[j][0];
            #pragma unroll
            for (int d4 = 0; d4 < 16; d4++) {
                float4 vv = *(const float4*)(vr + d4 * 4);
                acc[d4*4+0] += pw * vv.x;
                acc[d4*4+1] += pw * vv.y;
                acc[d4*4+2] += pw * vv.z;
                acc[d4*4+3] += pw * vv.w;
            }
        }
    }

    // Write attn output: (B, S, H, D)
    const float inv = 1.0f / lrun;
    float* op = out + (((size_t)(b * SS + p) * HH + h) * DD);
    #pragma unroll
    for (int d4 = 0; d4 < 16; d4++) {
        float4 o;
        o.x = acc[d4*4+0] * inv;
        o.y = acc[d4*4+1] * inv;
        o.z = acc[d4*4+2] * inv;
        o.w = acc[d4*4+3] * inv;
        *(float4*)(op + d4 * 4) = o;
    }
}

// ---------------------------------------------------------------------------
// Tail: next_k / next_v = last window of k / v, layout (B, W, H, D)
// ---------------------------------------------------------------------------
__global__ __launch_bounds__(256) void tail_kernel(float* __restrict__ out)
{
    const size_t OFF_K = (size_t)BB * SS * HH * DD;             // 4194304
    const size_t OFF_V = OFF_K + (size_t)BB * WW * HH * DD;     // 4718592
    int i = blockIdx.x * 256 + threadIdx.x;                     // < 524288
    int b = i / (WW * HH * DD);
    int r = i % (WW * HH * DD);
    int w = r / (HH * DD);
    int r2 = r % (HH * DD);
    int h = r2 / DD;
    int d = r2 % DD;
    size_t src = (((size_t)(b * HH + h) * SS + (SS - WW + w)) * DD + d);
    out[OFF_K + i] = g_k[src];
    out[OFF_V + i] = g_v[src];
}

// ---------------------------------------------------------------------------
extern "C" void kernel_launch(void* const* d_in, const int* in_sizes, int n_in,
                              void* d_out, int out_size)
{
    const float* xs       = (const float*)d_in[0];
    const float* prev_k   = (const float*)d_in[1];
    const float* prev_v   = (const float*)d_in[2];
    const float* w_q      = (const float*)d_in[3];
    const float* w_k      = (const float*)d_in[4];
    const float* w_v      = (const float*)d_in[5];
    const float* rel_bias = (const float*)d_in[6];
    float* out = (float*)d_out;

    dim3 pg(64, 4, 3);                 // M/128, N/128, {q,k,v}
    proj_kernel<<<pg, 256>>>(xs, w_q, w_k, w_v);

    dim3 ag(4, HH, BB * NWIN);         // query chunks, heads, batch*windows
    attn_kernel<<<ag, 128>>>(prev_k, prev_v, rel_bias, out);

    tail_kernel<<<2048, 256>>>(out);
}